// round 1
// baseline (speedup 1.0000x reference)
#include <cuda_runtime.h>
#include <cuda_bf16.h>
#include <math.h>

// SSD detection post-processing.
// Inputs (metadata order):
//   d_in[0]: loc_data   [64, 72192, 4] float32
//   d_in[1]: conf_data  [64*72192, 2]  float32
//   d_in[2]: prior_data [72192, 4]     float32
// Output: [64, 2, 200, 5] float32  (class 0 all zeros; class 1 = NMS results)

#define NUM_PRIORS 72192
#define BATCH      64
#define TOP_K      200
#define CAND_BUF   8192
#define HIST_BINS  4096
#define CONF_TH    0.01f
#define NMS_TH     0.45f

struct Smem {
    unsigned long long cand[CAND_BUF];  // 64 KB
    int   hist[HIST_BINS];              // 16 KB
    float bx0[TOP_K];
    float by0[TOP_K];
    float bx1[TOP_K];
    float by1[TOP_K];
    float score[TOP_K];
    float area[TOP_K];
    int   keep[TOP_K];
    int   pos[TOP_K];
    int   counter;
    int   thrbin;
};

__global__ __launch_bounds__(1024, 1)
void ssd_kernel(const float* __restrict__ loc,
                const float2* __restrict__ conf2,   // [B*P] of (c0, c1)
                const float* __restrict__ prior,
                float* __restrict__ out)
{
    extern __shared__ unsigned char smem_raw[];
    Smem& s = *reinterpret_cast<Smem*>(smem_raw);

    const int b   = blockIdx.x;
    const int tid = threadIdx.x;
    const int NT  = blockDim.x;

    // ---- init ----
    for (int i = tid; i < HIST_BINS; i += NT) s.hist[i] = 0;
    for (int i = tid; i < CAND_BUF;  i += NT) s.cand[i] = 0ull;
    if (tid == 0) { s.counter = 0; s.thrbin = 0; }
    __syncthreads();

    const float2* cb = conf2 + (size_t)b * NUM_PRIORS;

    // ---- pass 1: histogram of class-1 score bits (positive floats sort as ints) ----
    for (int p = tid; p < NUM_PRIORS; p += NT) {
        float sc = cb[p].y;
        if (sc > CONF_TH) {
            atomicAdd(&s.hist[__float_as_uint(sc) >> 20], 1);
        }
    }
    __syncthreads();

    // ---- find coarse threshold bin (cumulative from top >= TOP_K) ----
    if (tid == 0) {
        int cum = 0, thr = 0;
        for (int v = HIST_BINS - 1; v >= 0; --v) {
            cum += s.hist[v];
            if (cum >= TOP_K) { thr = v; break; }
        }
        s.thrbin = thr;
    }
    __syncthreads();
    const int thr = s.thrbin;

    // ---- pass 2: gather candidate keys: (score_bits << 32) | ~idx ----
    // key order = score desc, then index asc (matches jax.lax.top_k ties).
    for (int p = tid; p < NUM_PRIORS; p += NT) {
        float sc = cb[p].y;
        unsigned ub = __float_as_uint(sc);
        if (sc > CONF_TH && (int)(ub >> 20) >= thr) {
            int q = atomicAdd(&s.counter, 1);
            if (q < CAND_BUF) {
                s.cand[q] = ((unsigned long long)ub << 32) | (unsigned)(~p);
            }
        }
    }
    __syncthreads();

    // ---- bitonic sort CAND_BUF keys, descending ----
    for (int k2 = 2; k2 <= CAND_BUF; k2 <<= 1) {
        for (int j = k2 >> 1; j > 0; j >>= 1) {
            for (int i = tid; i < CAND_BUF; i += NT) {
                int ixj = i ^ j;
                if (ixj > i) {
                    unsigned long long a = s.cand[i];
                    unsigned long long c = s.cand[ixj];
                    bool up = (i & k2) == 0;           // descending overall
                    if (up ? (a < c) : (a > c)) {
                        s.cand[i] = c;
                        s.cand[ixj] = a;
                    }
                }
            }
            __syncthreads();
        }
    }

    // ---- decode top-200 boxes ----
    if (tid < TOP_K) {
        unsigned long long key = s.cand[tid];
        float sc  = __uint_as_float((unsigned)(key >> 32));
        int   idx = (int)(~(unsigned)key);
        bool valid = sc > CONF_TH;
        float x0 = 0.f, y0 = 0.f, x1 = 0.f, y1 = 0.f;
        if (valid) {
            const float* l  = loc   + ((size_t)b * NUM_PRIORS + idx) * 4;
            const float* pr = prior + (size_t)idx * 4;
            float lx = l[0],  ly = l[1],  lz = l[2],  lw = l[3];
            float pcx = pr[0], pcy = pr[1], pw = pr[2], ph = pr[3];
            float cx = pcx + lx * 0.1f * pw;
            float cy = pcy + ly * 0.1f * ph;
            float w  = pw * expf(lz * 0.2f);
            float h  = ph * expf(lw * 0.2f);
            x0 = cx - w * 0.5f;
            y0 = cy - h * 0.5f;
            x1 = cx + w * 0.5f;
            y1 = cy + h * 0.5f;
        }
        s.bx0[tid] = x0; s.by0[tid] = y0;
        s.bx1[tid] = x1; s.by1[tid] = y1;
        s.score[tid] = sc;
        s.area[tid]  = (x1 - x0) * (y1 - y0);
        s.keep[tid]  = valid ? 1 : 0;
    }
    __syncthreads();

    // ---- greedy NMS: serial i, parallel j ----
    for (int i = 0; i < TOP_K; ++i) {
        if (tid > i && tid < TOP_K && s.keep[i] && s.keep[tid]) {
            float xx0 = fmaxf(s.bx0[i], s.bx0[tid]);
            float yy0 = fmaxf(s.by0[i], s.by0[tid]);
            float xx1 = fminf(s.bx1[i], s.bx1[tid]);
            float yy1 = fminf(s.by1[i], s.by1[tid]);
            float w = fmaxf(xx1 - xx0, 0.f);
            float h = fmaxf(yy1 - yy0, 0.f);
            float inter = w * h;
            float uni = s.area[i] + s.area[tid] - inter;
            float iou = inter / fmaxf(uni, 1e-12f);
            if (iou > NMS_TH) s.keep[tid] = 0;
        }
        __syncthreads();
    }

    // ---- compact positions ----
    if (tid == 0) {
        int c = 0;
        for (int t = 0; t < TOP_K; ++t) {
            s.pos[t] = s.keep[t] ? c++ : -1;
        }
    }
    __syncthreads();

    // ---- write output: zero both class slices, then scatter kept rows into class 1 ----
    float* ob = out + (size_t)b * 2 * TOP_K * 5;
    for (int i = tid; i < 2 * TOP_K * 5; i += NT) ob[i] = 0.f;
    __syncthreads();

    if (tid < TOP_K && s.pos[tid] >= 0) {
        float* r = ob + (size_t)TOP_K * 5 + (size_t)s.pos[tid] * 5;
        r[0] = s.score[tid];
        r[1] = s.bx0[tid];
        r[2] = s.by0[tid];
        r[3] = s.bx1[tid];
        r[4] = s.by1[tid];
    }
}

extern "C" void kernel_launch(void* const* d_in, const int* in_sizes, int n_in,
                              void* d_out, int out_size)
{
    const float*  loc   = (const float*)d_in[0];
    const float2* conf2 = (const float2*)d_in[1];
    const float*  prior = (const float*)d_in[2];
    float* out = (float*)d_out;

    const int smem_bytes = (int)sizeof(Smem);
    cudaFuncSetAttribute(ssd_kernel, cudaFuncAttributeMaxDynamicSharedMemorySize, smem_bytes);
    ssd_kernel<<<BATCH, 1024, smem_bytes>>>(loc, conf2, prior, out);
}

// round 2
// speedup vs baseline: 2.4334x; 2.4334x over previous
#include <cuda_runtime.h>
#include <cuda_bf16.h>
#include <math.h>

// SSD detection post-processing.
//   d_in[0]: loc_data   [64, 72192, 4] float32
//   d_in[1]: conf_data  [64*72192, 2]  float32
//   d_in[2]: prior_data [72192, 4]     float32
// Output: [64, 2, 200, 5] float32 (class 0 zeros; class 1 = NMS results)

#define NUM_PRIORS 72192
#define BATCH      64
#define TOP_K      200
#define CAND_BUF   512
#define HIST_BINS  4096
#define BIN_SHIFT  14
#define BIN_OFF    61440        // 0x3C000000 >> 14  (= 0.0078125f); all sc > 0.01 map >= 143
#define CONF_TH    0.01f
#define NMS_TH     0.45f

struct Smem {
    unsigned long long cand[CAND_BUF];  // 4 KB
    int   hist[HIST_BINS];              // 16 KB
    float bx0[TOP_K];
    float by0[TOP_K];
    float bx1[TOP_K];
    float by1[TOP_K];
    float score[TOP_K];
    float area[TOP_K];
    int   keep[TOP_K];
    int   pos[TOP_K];
    int   counter;
    int   thrbin;
};

__device__ __forceinline__ int score_bin(unsigned ub) {
    int b = (int)(ub >> BIN_SHIFT) - BIN_OFF;
    return b < 0 ? 0 : (b > HIST_BINS - 1 ? HIST_BINS - 1 : b);
}

__global__ __launch_bounds__(1024, 1)
void ssd_kernel(const float* __restrict__ loc,
                const float2* __restrict__ conf2,
                const float* __restrict__ prior,
                float* __restrict__ out)
{
    extern __shared__ unsigned char smem_raw[];
    Smem& s = *reinterpret_cast<Smem*>(smem_raw);

    const int b   = blockIdx.x;
    const int tid = threadIdx.x;
    const int NT  = blockDim.x;

    for (int i = tid; i < HIST_BINS; i += NT) s.hist[i] = 0;
    for (int i = tid; i < CAND_BUF;  i += NT) s.cand[i] = 0ull;
    if (tid == 0) { s.counter = 0; s.thrbin = 0; }
    __syncthreads();

    const float2* cb = conf2 + (size_t)b * NUM_PRIORS;

    // ---- pass 1: fine histogram of class-1 score bits ----
    for (int p = tid; p < NUM_PRIORS; p += NT) {
        float sc = cb[p].y;
        if (sc > CONF_TH) {
            atomicAdd(&s.hist[score_bin(__float_as_uint(sc))], 1);
        }
    }
    __syncthreads();

    // ---- threshold bin: cumulative from top >= TOP_K (expect ~15 iterations) ----
    if (tid == 0) {
        int cum = 0, thr = 0;
        for (int v = HIST_BINS - 1; v >= 0; --v) {
            cum += s.hist[v];
            if (cum >= TOP_K) { thr = v; break; }
        }
        s.thrbin = thr;
    }
    __syncthreads();
    const int thr = s.thrbin;

    // ---- pass 2: gather keys (score desc, index asc via (bits<<32)|~p) ----
    for (int p = tid; p < NUM_PRIORS; p += NT) {
        float sc = cb[p].y;
        unsigned ub = __float_as_uint(sc);
        if (sc > CONF_TH && score_bin(ub) >= thr) {
            int q = atomicAdd(&s.counter, 1);
            if (q < CAND_BUF) {
                s.cand[q] = ((unsigned long long)ub << 32) | (unsigned)(~p);
            }
        }
    }
    __syncthreads();

    // ---- bitonic sort CAND_BUF keys, descending ----
    for (int k2 = 2; k2 <= CAND_BUF; k2 <<= 1) {
        for (int j = k2 >> 1; j > 0; j >>= 1) {
            int i = tid;                       // CAND_BUF/2 useful compares; NT >= CAND_BUF
            if (i < CAND_BUF) {
                int ixj = i ^ j;
                if (ixj > i) {
                    unsigned long long a = s.cand[i];
                    unsigned long long c = s.cand[ixj];
                    bool up = (i & k2) == 0;
                    if (up ? (a < c) : (a > c)) {
                        s.cand[i] = c;
                        s.cand[ixj] = a;
                    }
                }
            }
            __syncthreads();
        }
    }

    // ---- decode top-200 ----
    if (tid < TOP_K) {
        unsigned long long key = s.cand[tid];
        float sc  = __uint_as_float((unsigned)(key >> 32));
        int   idx = (int)(~(unsigned)key);
        bool valid = sc > CONF_TH;
        float x0 = 0.f, y0 = 0.f, x1 = 0.f, y1 = 0.f;
        if (valid) {
            const float4 l  = __ldg((const float4*)(loc + ((size_t)b * NUM_PRIORS + idx) * 4));
            const float4 pr = __ldg((const float4*)(prior + (size_t)idx * 4));
            float cx = pr.x + l.x * 0.1f * pr.z;
            float cy = pr.y + l.y * 0.1f * pr.w;
            float w  = pr.z * expf(l.z * 0.2f);
            float h  = pr.w * expf(l.w * 0.2f);
            x0 = cx - w * 0.5f;
            y0 = cy - h * 0.5f;
            x1 = cx + w * 0.5f;
            y1 = cy + h * 0.5f;
        }
        s.bx0[tid] = x0; s.by0[tid] = y0;
        s.bx1[tid] = x1; s.by1[tid] = y1;
        s.score[tid] = sc;
        s.area[tid]  = (x1 - x0) * (y1 - y0);
        s.keep[tid]  = valid ? 1 : 0;
    }
    __syncthreads();

    // ---- greedy NMS: warp 0 only, serial i, lanes parallel over j ----
    if (tid < 32) {
        for (int i = 0; i < TOP_K; ++i) {
            if (s.keep[i]) {
                float ix0 = s.bx0[i], iy0 = s.by0[i];
                float ix1 = s.bx1[i], iy1 = s.by1[i];
                float ia  = s.area[i];
                for (int j = i + 1 + tid; j < TOP_K; j += 32) {
                    if (s.keep[j]) {
                        float w = fminf(ix1, s.bx1[j]) - fmaxf(ix0, s.bx0[j]);
                        float h = fminf(iy1, s.by1[j]) - fmaxf(iy0, s.by0[j]);
                        w = fmaxf(w, 0.f); h = fmaxf(h, 0.f);
                        float inter = w * h;
                        float uni = ia + s.area[j] - inter;
                        if (inter > NMS_TH * fmaxf(uni, 1e-12f)) s.keep[j] = 0;
                    }
                }
            }
            __syncwarp();
        }
        // compact positions (lane 0 serial)
        if (tid == 0) {
            int c = 0;
            for (int t = 0; t < TOP_K; ++t)
                s.pos[t] = s.keep[t] ? c++ : -1;
        }
    }
    __syncthreads();

    // ---- write output ----
    float* ob = out + (size_t)b * 2 * TOP_K * 5;
    for (int i = tid; i < 2 * TOP_K * 5; i += NT) ob[i] = 0.f;
    __syncthreads();

    if (tid < TOP_K && s.pos[tid] >= 0) {
        float* r = ob + (size_t)TOP_K * 5 + (size_t)s.pos[tid] * 5;
        r[0] = s.score[tid];
        r[1] = s.bx0[tid];
        r[2] = s.by0[tid];
        r[3] = s.bx1[tid];
        r[4] = s.by1[tid];
    }
}

extern "C" void kernel_launch(void* const* d_in, const int* in_sizes, int n_in,
                              void* d_out, int out_size)
{
    const float*  locp  = (const float*)d_in[0];
    const float2* conf2 = (const float2*)d_in[1];
    const float*  prior = (const float*)d_in[2];
    float* out = (float*)d_out;

    const int smem_bytes = (int)sizeof(Smem);
    cudaFuncSetAttribute(ssd_kernel, cudaFuncAttributeMaxDynamicSharedMemorySize, smem_bytes);
    ssd_kernel<<<BATCH, 1024, smem_bytes>>>(locp, conf2, prior, out);
}

// round 3
// speedup vs baseline: 4.7456x; 1.9502x over previous
#include <cuda_runtime.h>
#include <cuda_bf16.h>
#include <math.h>

// SSD detection post-processing.
//   d_in[0]: loc_data   [64, 72192, 4] float32
//   d_in[1]: conf_data  [64*72192, 2]  float32
//   d_in[2]: prior_data [72192, 4]     float32
// Output: [64, 2, 200, 5] float32 (class 0 zeros; class 1 = NMS results)

#define NUM_PRIORS 72192
#define BATCH      64
#define TOP_K      200
#define CAND_BUF   1024
#define HIST_BINS  4096
#define BIN_SHIFT  14
#define BIN_OFF    61440
#define CONF_TH    0.01f
#define NMS_TH     0.45f
#define SAMPLE_STRIDE 16
#define SAMPLED_TARGET 24   // expected actual survivors ~384 in [200,1024]
#define NWORDS 7            // ceil(200/32)

struct Smem {
    unsigned long long cand[CAND_BUF];   // 8 KB
    int      hist[HIST_BINS];            // 16 KB
    float    bx0[TOP_K], by0[TOP_K], bx1[TOP_K], by1[TOP_K];
    float    score[TOP_K], area[TOP_K];
    unsigned sup[TOP_K][8];              // suppression bitmask rows (padded)
    unsigned keepw[8];                   // final keep bitmask words
    int      counter;
    int      thrbin;
    int      fallback;
};

__device__ __forceinline__ int score_bin(unsigned ub) {
    int v = (int)(ub >> BIN_SHIFT) - BIN_OFF;
    return v < 0 ? 0 : (v > HIST_BINS - 1 ? HIST_BINS - 1 : v);
}

__global__ __launch_bounds__(1024, 1)
void ssd_kernel(const float* __restrict__ loc,
                const float2* __restrict__ conf2,
                const float* __restrict__ prior,
                float* __restrict__ out)
{
    extern __shared__ unsigned char smem_raw[];
    Smem& s = *reinterpret_cast<Smem*>(smem_raw);

    const int b   = blockIdx.x;
    const int tid = threadIdx.x;
    const int NT  = blockDim.x;

    for (int i = tid; i < HIST_BINS; i += NT) s.hist[i] = 0;
    for (int i = tid; i < CAND_BUF;  i += NT) s.cand[i] = 0ull;
    if (tid == 0) { s.counter = 0; s.thrbin = 0; s.fallback = 0; }
    __syncthreads();

    const float2* cb = conf2 + (size_t)b * NUM_PRIORS;

    // ---- pass 1: SAMPLED histogram (1/16 of elements -> ~4.5k atomics) ----
    for (int i = tid; i < NUM_PRIORS / SAMPLE_STRIDE; i += NT) {
        float sc = cb[i * SAMPLE_STRIDE].y;
        if (sc > CONF_TH) atomicAdd(&s.hist[score_bin(__float_as_uint(sc))], 1);
    }
    __syncthreads();

    // ---- speculative threshold: sampled cum-from-top >= SAMPLED_TARGET ----
    if (tid == 0) {
        int cum = 0, thr = 0;
        for (int v = HIST_BINS - 1; v >= 0; --v) {
            cum += s.hist[v];
            if (cum >= SAMPLED_TARGET) { thr = v; break; }
        }
        s.thrbin = thr;
    }
    __syncthreads();
    int thr = s.thrbin;

    // ---- pass 2: gather keys (score desc, index asc via (bits<<32)|~p) ----
    for (int p = tid; p < NUM_PRIORS; p += NT) {
        float sc = cb[p].y;
        unsigned ub = __float_as_uint(sc);
        if (sc > CONF_TH && score_bin(ub) >= thr) {
            int q = atomicAdd(&s.counter, 1);
            if (q < CAND_BUF)
                s.cand[q] = ((unsigned long long)ub << 32) | (unsigned)(~p);
        }
    }
    __syncthreads();

    // ---- correctness guard: exact fallback if speculation bracketed wrong ----
    if ((s.counter > CAND_BUF) || (s.counter < TOP_K && thr > 0)) {
        // exact full histogram
        for (int i = tid; i < HIST_BINS; i += NT) s.hist[i] = 0;
        __syncthreads();
        for (int p = tid; p < NUM_PRIORS; p += NT) {
            float sc = cb[p].y;
            if (sc > CONF_TH) atomicAdd(&s.hist[score_bin(__float_as_uint(sc))], 1);
        }
        __syncthreads();
        if (tid == 0) {
            int cum = 0, t2 = 0;
            for (int v = HIST_BINS - 1; v >= 0; --v) {
                cum += s.hist[v];
                if (cum >= TOP_K) { t2 = v; break; }
            }
            s.thrbin = t2;
            s.counter = 0;
        }
        __syncthreads();
        thr = s.thrbin;
        for (int i = tid; i < CAND_BUF; i += NT) s.cand[i] = 0ull;
        __syncthreads();
        for (int p = tid; p < NUM_PRIORS; p += NT) {
            float sc = cb[p].y;
            unsigned ub = __float_as_uint(sc);
            if (sc > CONF_TH && score_bin(ub) >= thr) {
                int q = atomicAdd(&s.counter, 1);
                if (q < CAND_BUF)
                    s.cand[q] = ((unsigned long long)ub << 32) | (unsigned)(~p);
            }
        }
        __syncthreads();
    }

    // ---- bitonic sort CAND_BUF (=NT) keys, descending; thread owns slot tid ----
    for (int k2 = 2; k2 <= CAND_BUF; k2 <<= 1) {
        for (int j = k2 >> 1; j > 0; j >>= 1) {
            int i = tid;
            int ixj = i ^ j;
            if (ixj > i) {
                unsigned long long a = s.cand[i];
                unsigned long long c = s.cand[ixj];
                bool up = (i & k2) == 0;
                if (up ? (a < c) : (a > c)) { s.cand[i] = c; s.cand[ixj] = a; }
            }
            __syncthreads();
        }
    }

    // ---- decode top-200 ----
    if (tid < TOP_K) {
        unsigned long long key = s.cand[tid];
        float sc  = __uint_as_float((unsigned)(key >> 32));
        int   idx = (int)(~(unsigned)key);
        bool valid = sc > CONF_TH;
        float x0 = 0.f, y0 = 0.f, x1 = 0.f, y1 = 0.f;
        if (valid) {
            const float4 l  = __ldg((const float4*)(loc + ((size_t)b * NUM_PRIORS + idx) * 4));
            const float4 pr = __ldg((const float4*)(prior + (size_t)idx * 4));
            float cx = pr.x + l.x * 0.1f * pr.z;
            float cy = pr.y + l.y * 0.1f * pr.w;
            float w  = pr.z * expf(l.z * 0.2f);
            float h  = pr.w * expf(l.w * 0.2f);
            x0 = cx - w * 0.5f; y0 = cy - h * 0.5f;
            x1 = cx + w * 0.5f; y1 = cy + h * 0.5f;
        }
        s.bx0[tid] = x0; s.by0[tid] = y0;
        s.bx1[tid] = x1; s.by1[tid] = y1;
        s.score[tid] = sc;
        s.area[tid]  = (x1 - x0) * (y1 - y0);
    }
    if (tid < 8) s.keepw[tid] = 0u;
    __syncthreads();

    // ---- build 200x200 suppression bitmask in parallel (ballots) ----
    {
        const int warp = tid >> 5, lane = tid & 31;
        for (int i = warp; i < TOP_K; i += 32) {
            float ix0 = s.bx0[i], iy0 = s.by0[i];
            float ix1 = s.bx1[i], iy1 = s.by1[i];
            float ia  = s.area[i];
            for (int w = 0; w < NWORDS; ++w) {
                int j = (w << 5) + lane;
                bool sup = false;
                if (j < TOP_K && j > i) {
                    float ww = fminf(ix1, s.bx1[j]) - fmaxf(ix0, s.bx0[j]);
                    float hh = fminf(iy1, s.by1[j]) - fmaxf(iy0, s.by0[j]);
                    ww = fmaxf(ww, 0.f); hh = fmaxf(hh, 0.f);
                    float inter = ww * hh;
                    float uni = ia + s.area[j] - inter;
                    sup = inter > NMS_TH * fmaxf(uni, 1e-12f);
                }
                unsigned bal = __ballot_sync(0xffffffffu, sup);
                if (lane == 0) s.sup[i][w] = bal;
            }
        }
        // initial keep = valid (score > CONF_TH)
        if (warp < NWORDS) {
            int j = (warp << 5) + lane;
            bool v = (j < TOP_K) && (s.score[j] > CONF_TH);
            unsigned bal = __ballot_sync(0xffffffffu, v);
            if (lane == 0) s.keepw[warp] = bal;
        }
    }
    __syncthreads();

    // ---- warp-serial NMS fold: lanes own mask words ----
    if (tid < 32) {
        unsigned mask = (tid < NWORDS) ? s.keepw[tid] : 0u;
        for (int i = 0; i < TOP_K; ++i) {
            unsigned wi = __shfl_sync(0xffffffffu, mask, i >> 5);
            if ((wi >> (i & 31)) & 1u) {
                if (tid < NWORDS) mask &= ~s.sup[i][tid];
            }
        }
        if (tid < NWORDS) s.keepw[tid] = mask;
    }
    __syncthreads();

    // ---- write output ----
    float* ob = out + (size_t)b * 2 * TOP_K * 5;
    for (int i = tid; i < 2 * TOP_K * 5; i += NT) ob[i] = 0.f;
    __syncthreads();

    if (tid < TOP_K) {
        int w = tid >> 5, bit = tid & 31;
        unsigned mw = s.keepw[w];
        if ((mw >> bit) & 1u) {
            int pos = 0;
            for (int k = 0; k < w; ++k) pos += __popc(s.keepw[k]);
            pos += __popc(mw & ((1u << bit) - 1u));
            float* r = ob + (size_t)TOP_K * 5 + (size_t)pos * 5;
            r[0] = s.score[tid];
            r[1] = s.bx0[tid];
            r[2] = s.by0[tid];
            r[3] = s.bx1[tid];
            r[4] = s.by1[tid];
        }
    }
}

extern "C" void kernel_launch(void* const* d_in, const int* in_sizes, int n_in,
                              void* d_out, int out_size)
{
    const float*  locp  = (const float*)d_in[0];
    const float2* conf2 = (const float2*)d_in[1];
    const float*  prior = (const float*)d_in[2];
    float* out = (float*)d_out;

    const int smem_bytes = (int)sizeof(Smem);
    cudaFuncSetAttribute(ssd_kernel, cudaFuncAttributeMaxDynamicSharedMemorySize, smem_bytes);
    ssd_kernel<<<BATCH, 1024, smem_bytes>>>(locp, conf2, prior, out);
}

// round 4
// speedup vs baseline: 4.9616x; 1.0455x over previous
#include <cuda_runtime.h>
#include <cuda_bf16.h>
#include <math.h>

// SSD detection post-processing, two-phase.
//   d_in[0]: loc_data   [64, 72192, 4] float32
//   d_in[1]: conf_data  [64*72192, 2]  float32
//   d_in[2]: prior_data [72192, 4]     float32
// Output: [64, 2, 200, 5] float32 (class 0 zeros; class 1 = NMS results)

#define NUM_PRIORS 72192
#define BATCH      64
#define TOP_K      200
#define CAND_BUF   1024
#define HIST_BINS  4096
#define BIN_SHIFT  14
#define BIN_OFF    61440
#define CONF_TH    0.01f
#define NMS_TH     0.45f
#define SPEC_TH    0.9940f      // expected ~433 survivors/batch (uniform scores)
#define NWORDS     7            // ceil(200/32)
#define SLICES     8
#define PRIORS_PER_SLICE (NUM_PRIORS / SLICES)   // 9024

// ---- global scratch (no allocation allowed) ----
__device__ unsigned long long g_cand[BATCH][CAND_BUF];
__device__ int g_cnt[BATCH];     // gathered count (may exceed CAND_BUF logically)
__device__ int g_nconf[BATCH];   // count of scores > CONF_TH

// ============================ kernel Z: zero counters ============================
__global__ void zero_kernel() {
    int i = threadIdx.x;
    if (i < BATCH) { g_cnt[i] = 0; g_nconf[i] = 0; }
}

// ============================ kernel A: scan + gather ============================
__global__ __launch_bounds__(256)
void scan_kernel(const float4* __restrict__ conf4)   // [B * P/2] of (c0,c1,c0,c1)
{
    const int b     = blockIdx.y;
    const int slice = blockIdx.x;
    const int tid   = threadIdx.x;

    const int pair_base = (b * NUM_PRIORS + slice * PRIORS_PER_SLICE) >> 1;
    const int npairs    = PRIORS_PER_SLICE >> 1;          // 4512
    const int p_base    = slice * PRIORS_PER_SLICE;

    int nconf = 0;
    for (int i = tid; i < npairs; i += 256) {
        float4 v = conf4[pair_base + i];
        int p0 = p_base + 2 * i;
        // prior p0: score v.y ; prior p0+1: score v.w
        nconf += (v.y > CONF_TH) + (v.w > CONF_TH);
        if (v.y >= SPEC_TH) {
            int q = atomicAdd(&g_cnt[b], 1);
            if (q < CAND_BUF)
                g_cand[b][q] = ((unsigned long long)__float_as_uint(v.y) << 32)
                             | (unsigned)(~p0);
        }
        if (v.w >= SPEC_TH) {
            int q = atomicAdd(&g_cnt[b], 1);
            if (q < CAND_BUF)
                g_cand[b][q] = ((unsigned long long)__float_as_uint(v.w) << 32)
                             | (unsigned)(~(p0 + 1));
        }
    }
    // warp-reduce nconf, one atomic per warp
    #pragma unroll
    for (int o = 16; o > 0; o >>= 1) nconf += __shfl_down_sync(0xffffffffu, nconf, o);
    if ((tid & 31) == 0 && nconf) atomicAdd(&g_nconf[b], nconf);
}

// ============================ kernel B: sort + NMS + write ============================
struct Smem {
    unsigned long long cand[CAND_BUF];   // 8 KB
    int      hist[HIST_BINS];            // 16 KB (fallback only)
    float    bx0[TOP_K], by0[TOP_K], bx1[TOP_K], by1[TOP_K];
    float    score[TOP_K], area[TOP_K];
    unsigned sup[TOP_K][8];
    unsigned keepw[8];
    int      counter;
    int      thrbin;
};

__device__ __forceinline__ int score_bin(unsigned ub) {
    int v = (int)(ub >> BIN_SHIFT) - BIN_OFF;
    return v < 0 ? 0 : (v > HIST_BINS - 1 ? HIST_BINS - 1 : v);
}

__global__ __launch_bounds__(1024, 1)
void final_kernel(const float* __restrict__ loc,
                  const float2* __restrict__ conf2,
                  const float* __restrict__ prior,
                  float* __restrict__ out)
{
    extern __shared__ unsigned char smem_raw[];
    Smem& s = *reinterpret_cast<Smem*>(smem_raw);

    const int b   = blockIdx.x;
    const int tid = threadIdx.x;
    const int NT  = blockDim.x;

    const int cnt   = g_cnt[b];
    const int nconf = g_nconf[b];

    if (cnt <= CAND_BUF && (cnt >= TOP_K || cnt == nconf)) {
        // fast path: speculative gather was exact-bracketing
        s.cand[tid] = (tid < cnt) ? g_cand[b][tid] : 0ull;
        __syncthreads();
    } else {
        // ---- exact fallback: full histogram select within this CTA ----
        const float2* cb = conf2 + (size_t)b * NUM_PRIORS;
        for (int i = tid; i < HIST_BINS; i += NT) s.hist[i] = 0;
        if (tid == 0) { s.counter = 0; s.thrbin = 0; }
        __syncthreads();
        for (int p = tid; p < NUM_PRIORS; p += NT) {
            float sc = cb[p].y;
            if (sc > CONF_TH) atomicAdd(&s.hist[score_bin(__float_as_uint(sc))], 1);
        }
        __syncthreads();
        if (tid == 0) {
            int cum = 0, thr = 0;
            for (int v = HIST_BINS - 1; v >= 0; --v) {
                cum += s.hist[v];
                if (cum >= TOP_K) { thr = v; break; }
            }
            s.thrbin = thr;
        }
        __syncthreads();
        const int thr = s.thrbin;
        s.cand[tid] = 0ull;
        __syncthreads();
        for (int p = tid; p < NUM_PRIORS; p += NT) {
            float sc = cb[p].y;
            unsigned ub = __float_as_uint(sc);
            if (sc > CONF_TH && score_bin(ub) >= thr) {
                int q = atomicAdd(&s.counter, 1);
                if (q < CAND_BUF)
                    s.cand[q] = ((unsigned long long)ub << 32) | (unsigned)(~p);
            }
        }
        __syncthreads();
    }

    // ---- bitonic sort CAND_BUF (=NT) keys, descending ----
    for (int k2 = 2; k2 <= CAND_BUF; k2 <<= 1) {
        for (int j = k2 >> 1; j > 0; j >>= 1) {
            int i = tid;
            int ixj = i ^ j;
            if (ixj > i) {
                unsigned long long a = s.cand[i];
                unsigned long long c = s.cand[ixj];
                bool up = (i & k2) == 0;
                if (up ? (a < c) : (a > c)) { s.cand[i] = c; s.cand[ixj] = a; }
            }
            __syncthreads();
        }
    }

    // ---- decode top-200 ----
    if (tid < TOP_K) {
        unsigned long long key = s.cand[tid];
        float sc  = __uint_as_float((unsigned)(key >> 32));
        int   idx = (int)(~(unsigned)key);
        bool valid = sc > CONF_TH;
        float x0 = 0.f, y0 = 0.f, x1 = 0.f, y1 = 0.f;
        if (valid) {
            const float4 l  = __ldg((const float4*)(loc + ((size_t)b * NUM_PRIORS + idx) * 4));
            const float4 pr = __ldg((const float4*)(prior + (size_t)idx * 4));
            float cx = pr.x + l.x * 0.1f * pr.z;
            float cy = pr.y + l.y * 0.1f * pr.w;
            float w  = pr.z * expf(l.z * 0.2f);
            float h  = pr.w * expf(l.w * 0.2f);
            x0 = cx - w * 0.5f; y0 = cy - h * 0.5f;
            x1 = cx + w * 0.5f; y1 = cy + h * 0.5f;
        }
        s.bx0[tid] = x0; s.by0[tid] = y0;
        s.bx1[tid] = x1; s.by1[tid] = y1;
        s.score[tid] = sc;
        s.area[tid]  = (x1 - x0) * (y1 - y0);
    }
    if (tid < 8) s.keepw[tid] = 0u;
    __syncthreads();

    // ---- build 200x200 suppression bitmask (ballots) ----
    {
        const int warp = tid >> 5, lane = tid & 31;
        for (int i = warp; i < TOP_K; i += 32) {
            float ix0 = s.bx0[i], iy0 = s.by0[i];
            float ix1 = s.bx1[i], iy1 = s.by1[i];
            float ia  = s.area[i];
            for (int w = 0; w < NWORDS; ++w) {
                int j = (w << 5) + lane;
                bool sup = false;
                if (j < TOP_K && j > i) {
                    float ww = fminf(ix1, s.bx1[j]) - fmaxf(ix0, s.bx0[j]);
                    float hh = fminf(iy1, s.by1[j]) - fmaxf(iy0, s.by0[j]);
                    ww = fmaxf(ww, 0.f); hh = fmaxf(hh, 0.f);
                    float inter = ww * hh;
                    float uni = ia + s.area[j] - inter;
                    sup = inter > NMS_TH * fmaxf(uni, 1e-12f);
                }
                unsigned bal = __ballot_sync(0xffffffffu, sup);
                if (lane == 0) s.sup[i][w] = bal;
            }
        }
        if (warp < NWORDS) {
            int j = (warp << 5) + lane;
            bool v = (j < TOP_K) && (s.score[j] > CONF_TH);
            unsigned bal = __ballot_sync(0xffffffffu, v);
            if (lane == 0) s.keepw[warp] = bal;
        }
    }
    __syncthreads();

    // ---- warp-serial NMS fold ----
    if (tid < 32) {
        unsigned mask = (tid < NWORDS) ? s.keepw[tid] : 0u;
        for (int i = 0; i < TOP_K; ++i) {
            unsigned wi = __shfl_sync(0xffffffffu, mask, i >> 5);
            if ((wi >> (i & 31)) & 1u) {
                if (tid < NWORDS) mask &= ~s.sup[i][tid];
            }
        }
        if (tid < NWORDS) s.keepw[tid] = mask;
    }
    __syncthreads();

    // ---- write output ----
    float* ob = out + (size_t)b * 2 * TOP_K * 5;
    for (int i = tid; i < 2 * TOP_K * 5; i += NT) ob[i] = 0.f;
    __syncthreads();

    if (tid < TOP_K) {
        int w = tid >> 5, bit = tid & 31;
        unsigned mw = s.keepw[w];
        if ((mw >> bit) & 1u) {
            int pos = 0;
            for (int k = 0; k < w; ++k) pos += __popc(s.keepw[k]);
            pos += __popc(mw & ((1u << bit) - 1u));
            float* r = ob + (size_t)TOP_K * 5 + (size_t)pos * 5;
            r[0] = s.score[tid];
            r[1] = s.bx0[tid];
            r[2] = s.by0[tid];
            r[3] = s.bx1[tid];
            r[4] = s.by1[tid];
        }
    }
}

extern "C" void kernel_launch(void* const* d_in, const int* in_sizes, int n_in,
                              void* d_out, int out_size)
{
    const float*  locp  = (const float*)d_in[0];
    const float2* conf2 = (const float2*)d_in[1];
    const float4* conf4 = (const float4*)d_in[1];
    const float*  prior = (const float*)d_in[2];
    float* out = (float*)d_out;

    zero_kernel<<<1, 128>>>();

    dim3 gA(SLICES, BATCH);
    scan_kernel<<<gA, 256>>>(conf4);

    const int smem_bytes = (int)sizeof(Smem);
    cudaFuncSetAttribute(final_kernel, cudaFuncAttributeMaxDynamicSharedMemorySize, smem_bytes);
    final_kernel<<<BATCH, 1024, smem_bytes>>>(locp, conf2, prior, out);
}

// round 5
// speedup vs baseline: 6.2703x; 1.2638x over previous
#include <cuda_runtime.h>
#include <cuda_bf16.h>
#include <math.h>

// SSD detection post-processing, two-phase, self-resetting counters.
//   d_in[0]: loc_data   [64, 72192, 4] float32
//   d_in[1]: conf_data  [64*72192, 2]  float32
//   d_in[2]: prior_data [72192, 4]     float32
// Output: [64, 2, 200, 5] float32 (class 0 zeros; class 1 = NMS results)

#define NUM_PRIORS 72192
#define BATCH      64
#define TOP_K      200
#define CAND_BUF   512
#define HIST_BINS  4096
#define BIN_SHIFT  14
#define BIN_OFF    61440
#define CONF_TH    0.01f
#define NMS_TH     0.45f
#define SPEC_TH    0.9958f      // expected ~303 survivors/batch (uniform scores)
#define NWORDS     7            // ceil(200/32)
#define SLICES     16
#define PRIORS_PER_SLICE (NUM_PRIORS / SLICES)   // 4512
#define FINAL_NT   512

// ---- global scratch (zero-initialized at load; final_kernel re-zeroes) ----
__device__ unsigned long long g_cand[BATCH][CAND_BUF];
__device__ int g_cnt[BATCH];
__device__ int g_nconf[BATCH];

// ============================ kernel A: scan + gather ============================
__global__ __launch_bounds__(256)
void scan_kernel(const float4* __restrict__ conf4)
{
    const int b     = blockIdx.y;
    const int slice = blockIdx.x;
    const int tid   = threadIdx.x;

    const int pair_base = (b * NUM_PRIORS + slice * PRIORS_PER_SLICE) >> 1;
    const int npairs    = PRIORS_PER_SLICE >> 1;          // 2256
    const int p_base    = slice * PRIORS_PER_SLICE;

    int nconf = 0;
    for (int i = tid; i < npairs; i += 256) {
        float4 v = conf4[pair_base + i];
        int p0 = p_base + 2 * i;
        nconf += (v.y > CONF_TH) + (v.w > CONF_TH);
        if (v.y >= SPEC_TH) {
            int q = atomicAdd(&g_cnt[b], 1);
            if (q < CAND_BUF)
                g_cand[b][q] = ((unsigned long long)__float_as_uint(v.y) << 32)
                             | (unsigned)(~p0);
        }
        if (v.w >= SPEC_TH) {
            int q = atomicAdd(&g_cnt[b], 1);
            if (q < CAND_BUF)
                g_cand[b][q] = ((unsigned long long)__float_as_uint(v.w) << 32)
                             | (unsigned)(~(p0 + 1));
        }
    }
    #pragma unroll
    for (int o = 16; o > 0; o >>= 1) nconf += __shfl_down_sync(0xffffffffu, nconf, o);
    if ((tid & 31) == 0 && nconf) atomicAdd(&g_nconf[b], nconf);
}

// ============================ kernel B: sort + NMS + write ============================
struct Smem {
    unsigned long long cand[CAND_BUF];   // 4 KB
    int      hist[HIST_BINS];            // 16 KB (fallback only)
    float    bx0[TOP_K], by0[TOP_K], bx1[TOP_K], by1[TOP_K];
    float    score[TOP_K], area[TOP_K];
    unsigned sup[TOP_K][8];
    unsigned keepw[8];
    int      counter;
    int      thrbin;
};

__device__ __forceinline__ int score_bin(unsigned ub) {
    int v = (int)(ub >> BIN_SHIFT) - BIN_OFF;
    return v < 0 ? 0 : (v > HIST_BINS - 1 ? HIST_BINS - 1 : v);
}

__global__ __launch_bounds__(FINAL_NT, 1)
void final_kernel(const float* __restrict__ loc,
                  const float2* __restrict__ conf2,
                  const float* __restrict__ prior,
                  float* __restrict__ out)
{
    extern __shared__ unsigned char smem_raw[];
    Smem& s = *reinterpret_cast<Smem*>(smem_raw);

    const int b   = blockIdx.x;
    const int tid = threadIdx.x;
    const int NT  = FINAL_NT;

    const int cnt   = g_cnt[b];
    const int nconf = g_nconf[b];
    __syncthreads();                    // all reads done before reset
    if (tid == 0) { g_cnt[b] = 0; g_nconf[b] = 0; }   // self-reset for next replay

    unsigned long long v;               // key owned by this thread (slot tid)

    if (cnt <= CAND_BUF && (cnt >= TOP_K || cnt == nconf)) {
        v = (tid < cnt) ? g_cand[b][tid] : 0ull;
    } else {
        // ---- exact fallback: full histogram select ----
        const float2* cb = conf2 + (size_t)b * NUM_PRIORS;
        for (int i = tid; i < HIST_BINS; i += NT) s.hist[i] = 0;
        if (tid == 0) { s.counter = 0; s.thrbin = 0; }
        __syncthreads();
        for (int p = tid; p < NUM_PRIORS; p += NT) {
            float sc = cb[p].y;
            if (sc > CONF_TH) atomicAdd(&s.hist[score_bin(__float_as_uint(sc))], 1);
        }
        __syncthreads();
        if (tid == 0) {
            int cum = 0, thr = 0;
            for (int vb = HIST_BINS - 1; vb >= 0; --vb) {
                cum += s.hist[vb];
                if (cum >= TOP_K) { thr = vb; break; }
            }
            s.thrbin = thr;
        }
        __syncthreads();
        const int thr = s.thrbin;
        s.cand[tid] = 0ull;
        __syncthreads();
        for (int p = tid; p < NUM_PRIORS; p += NT) {
            float sc = cb[p].y;
            unsigned ub = __float_as_uint(sc);
            if (sc > CONF_TH && score_bin(ub) >= thr) {
                int q = atomicAdd(&s.counter, 1);
                if (q < CAND_BUF)
                    s.cand[q] = ((unsigned long long)ub << 32) | (unsigned)(~p);
            }
        }
        __syncthreads();
        v = s.cand[tid];
    }

    // ---- hybrid bitonic sort, 512 keys descending; thread owns slot tid ----
    // intra-warp steps (j<=16): shuffles, no barriers. cross-warp (j>=32): smem.
    #pragma unroll
    for (int k2 = 2; k2 <= CAND_BUF; k2 <<= 1) {
        #pragma unroll
        for (int j = k2 >> 1; j > 0; j >>= 1) {
            bool up    = (tid & k2) == 0;
            bool lower = (tid & j) == 0;
            bool keep_max = (up == lower);
            unsigned long long o;
            if (j >= 32) {
                s.cand[tid] = v;
                __syncthreads();
                o = s.cand[tid ^ j];
                __syncthreads();
            } else {
                o = __shfl_xor_sync(0xffffffffu, v, j);
            }
            v = keep_max ? (v >= o ? v : o) : (v >= o ? o : v);
        }
    }

    // ---- decode top-200 (keys live in registers of tid<200) ----
    if (tid < TOP_K) {
        float sc  = __uint_as_float((unsigned)(v >> 32));
        int   idx = (int)(~(unsigned)v);
        bool valid = sc > CONF_TH;
        float x0 = 0.f, y0 = 0.f, x1 = 0.f, y1 = 0.f;
        if (valid) {
            const float4 l  = __ldg((const float4*)(loc + ((size_t)b * NUM_PRIORS + idx) * 4));
            const float4 pr = __ldg((const float4*)(prior + (size_t)idx * 4));
            float cx = pr.x + l.x * 0.1f * pr.z;
            float cy = pr.y + l.y * 0.1f * pr.w;
            float w  = pr.z * expf(l.z * 0.2f);
            float h  = pr.w * expf(l.w * 0.2f);
            x0 = cx - w * 0.5f; y0 = cy - h * 0.5f;
            x1 = cx + w * 0.5f; y1 = cy + h * 0.5f;
        }
        s.bx0[tid] = x0; s.by0[tid] = y0;
        s.bx1[tid] = x1; s.by1[tid] = y1;
        s.score[tid] = sc;
        s.area[tid]  = (x1 - x0) * (y1 - y0);
    }
    if (tid < 8) s.keepw[tid] = 0u;
    __syncthreads();

    // ---- build 200x200 suppression bitmask (16 warps, ballots) ----
    {
        const int warp = tid >> 5, lane = tid & 31;
        for (int i = warp; i < TOP_K; i += FINAL_NT / 32) {
            float ix0 = s.bx0[i], iy0 = s.by0[i];
            float ix1 = s.bx1[i], iy1 = s.by1[i];
            float ia  = s.area[i];
            #pragma unroll
            for (int w = 0; w < NWORDS; ++w) {
                int j = (w << 5) + lane;
                bool sup = false;
                if (j < TOP_K && j > i) {
                    float ww = fminf(ix1, s.bx1[j]) - fmaxf(ix0, s.bx0[j]);
                    float hh = fminf(iy1, s.by1[j]) - fmaxf(iy0, s.by0[j]);
                    ww = fmaxf(ww, 0.f); hh = fmaxf(hh, 0.f);
                    float inter = ww * hh;
                    float uni = ia + s.area[j] - inter;
                    sup = inter > NMS_TH * fmaxf(uni, 1e-12f);
                }
                unsigned bal = __ballot_sync(0xffffffffu, sup);
                if (lane == 0) s.sup[i][w] = bal;
            }
        }
        if (warp < NWORDS) {
            int j = (warp << 5) + lane;
            bool val = (j < TOP_K) && (s.score[j] > CONF_TH);
            unsigned bal = __ballot_sync(0xffffffffu, val);
            if (lane == 0) s.keepw[warp] = bal;
        }
    }
    __syncthreads();

    // ---- warp-serial NMS fold ----
    if (tid < 32) {
        unsigned mask = (tid < NWORDS) ? s.keepw[tid] : 0u;
        for (int i = 0; i < TOP_K; ++i) {
            unsigned wi = __shfl_sync(0xffffffffu, mask, i >> 5);
            if ((wi >> (i & 31)) & 1u) {
                if (tid < NWORDS) mask &= ~s.sup[i][tid];
            }
        }
        if (tid < NWORDS) s.keepw[tid] = mask;
    }
    __syncthreads();

    // ---- write output ----
    float* ob = out + (size_t)b * 2 * TOP_K * 5;
    for (int i = tid; i < 2 * TOP_K * 5; i += NT) ob[i] = 0.f;
    __syncthreads();

    if (tid < TOP_K) {
        int w = tid >> 5, bit = tid & 31;
        unsigned mw = s.keepw[w];
        if ((mw >> bit) & 1u) {
            int pos = 0;
            #pragma unroll
            for (int k = 0; k < NWORDS; ++k)
                if (k < w) pos += __popc(s.keepw[k]);
            pos += __popc(mw & ((1u << bit) - 1u));
            float* r = ob + (size_t)TOP_K * 5 + (size_t)pos * 5;
            r[0] = s.score[tid];
            r[1] = s.bx0[tid];
            r[2] = s.by0[tid];
            r[3] = s.bx1[tid];
            r[4] = s.by1[tid];
        }
    }
}

extern "C" void kernel_launch(void* const* d_in, const int* in_sizes, int n_in,
                              void* d_out, int out_size)
{
    const float*  locp  = (const float*)d_in[0];
    const float2* conf2 = (const float2*)d_in[1];
    const float4* conf4 = (const float4*)d_in[1];
    const float*  prior = (const float*)d_in[2];
    float* out = (float*)d_out;

    dim3 gA(SLICES, BATCH);
    scan_kernel<<<gA, 256>>>(conf4);

    const int smem_bytes = (int)sizeof(Smem);
    cudaFuncSetAttribute(final_kernel, cudaFuncAttributeMaxDynamicSharedMemorySize, smem_bytes);
    final_kernel<<<BATCH, FINAL_NT, smem_bytes>>>(locp, conf2, prior, out);
}